// round 12
// baseline (speedup 1.0000x reference)
#include <cuda_runtime.h>
#include <cuda_bf16.h>
#include <mma.h>
#include <math.h>
#include <cstdint>
#include <cstddef>

using namespace nvcuda;

// Problem constants
#define TOK   4096          // B*S tokens
#define DM    1024          // d_model
#define NE    8             // experts
#define KSEL  2             // top-k
#define HD    4096          // expert dim
#define PD    256           // proj dim
#define TK    (TOK*KSEL)    // 8192 token-expert rows
#define CLAMP_MAX 4.6051701859880914f

// GEMM tiling
#define BMM 128
#define BNN 128
#define BKK 32
#define XLD 36              // smem leading dim (36 floats = 144B, 16B-aligned rows, conflict-spread)
#define CLD 132             // epilogue staging leading dim
#define NTILES 72           // max m-tiles: TK/128 + NE
#define GEMM_SMEM (4*128*XLD*4)   // 73728 B (2 X bufs + 2 B bufs); staging 128*132*4=67584 reuses it

// ---------------- device scratch (static; no allocation) ----------------
__device__ float g_proj[TOK*PD];
__device__ int   g_topk_e[TK];
__device__ float g_topk_w[TK];
__device__ float g_sumw[TOK];
__device__ int   g_count[NE];
__device__ int   g_offset[NE+1];
__device__ int   g_tileoff[NE+1];
__device__ int   g_cursor[NE];
__device__ int   g_token_of_row[TK];
__device__ float g_w_of_row[TK];
__device__ float g_H[(size_t)TK*HD];             // 134 MB (tf32-valued fp32)
__device__ float g_frac_acc[NE];
__device__ float g_inv_simnorm[NE];
__device__ float g_scale;

// tf32-pre-rounded copies (fp32 storage, tf32 bit patterns)
__device__ __align__(256) float g_x32[(size_t)TOK*DM];       // 16 MB
__device__ __align__(256) float g_A32[(size_t)NE*HD*DM];     // 134 MB
__device__ __align__(256) float g_B32[(size_t)NE*DM*HD];     // 134 MB

// ---------------- cp.async helpers ----------------
__device__ __forceinline__ void cp_async16(float* smem_dst, const float* gsrc, int src_bytes) {
    unsigned int s = (unsigned int)__cvta_generic_to_shared(smem_dst);
    asm volatile("cp.async.cg.shared.global [%0], [%1], 16, %2;\n"
                 :: "r"(s), "l"(gsrc), "r"(src_bytes));
}
__device__ __forceinline__ void cp_commit() { asm volatile("cp.async.commit_group;\n" ::: "memory"); }
__device__ __forceinline__ void cp_wait1()  { asm volatile("cp.async.wait_group 1;\n" ::: "memory"); }
__device__ __forceinline__ void cp_wait0()  { asm volatile("cp.async.wait_group 0;\n" ::: "memory"); }

// ---------------- small utility kernels ----------------
__global__ void reset_kernel() {
    int i = threadIdx.x;
    if (i < NE) { g_count[i] = 0; g_frac_acc[i] = 0.f; }
}

__global__ void prep_kernel(const float* __restrict__ sim, const float* __restrict__ temp) {
    int w = threadIdx.x >> 5, lane = threadIdx.x & 31;
    float ss = 0.f;
    for (int i = 0; i < PD/32; i++) {
        float v = sim[(lane + 32*i)*NE + w];
        ss += v*v;
    }
    #pragma unroll
    for (int off = 16; off; off >>= 1) ss += __shfl_xor_sync(0xffffffff, ss, off);
    if (lane == 0) g_inv_simnorm[w] = 1.f / fmaxf(sqrtf(ss), 1e-12f);
    if (threadIdx.x == 0) g_scale = expf(fminf(temp[0], CLAMP_MAX));
}

// pre-round fp32 -> tf32 bit patterns (RN), float4-vectorized.
// Destination is selected IN DEVICE CODE (device symbols must never be passed
// as host-side kernel arguments: on GB300 the host shadow address is
// ATS-accessible and the write silently lands in host memory).
__global__ void tf32_round_kernel(const float* __restrict__ src, int which, int n4) {
    float* dst = (which == 0) ? g_x32 : (which == 1) ? g_A32 : g_B32;
    int i = blockIdx.x * blockDim.x + threadIdx.x;
    if (i >= n4) return;
    float4 v = reinterpret_cast<const float4*>(src)[i];
    v.x = wmma::__float_to_tf32(v.x);
    v.y = wmma::__float_to_tf32(v.y);
    v.z = wmma::__float_to_tf32(v.z);
    v.w = wmma::__float_to_tf32(v.w);
    reinterpret_cast<float4*>(dst)[i] = v;
}

// ---------------- projection: proj = x @ Wp^T + bp (fp32 SIMT, exact) ----------------
__global__ void proj_kernel(const float* __restrict__ x, const float* __restrict__ Wp,
                            const float* __restrict__ bp) {
    const int BM = 64, BN = 64, BK = 16;
    __shared__ float Xs[BK][BM+2];
    __shared__ float Ws[BK][BN+2];
    int m0 = blockIdx.x * BM, n0 = blockIdx.y * BN;
    int tid = threadIdx.x;
    int ty = tid >> 4, tx = tid & 15;
    float acc[4][4];
    #pragma unroll
    for (int i = 0; i < 4; i++)
        #pragma unroll
        for (int j = 0; j < 4; j++) acc[i][j] = 0.f;

    for (int k0 = 0; k0 < DM; k0 += BK) {
        for (int idx = tid; idx < BM*BK; idx += 256) {
            int m = idx >> 4, k = idx & 15;
            Xs[k][m] = x[(size_t)(m0+m)*DM + k0 + k];
            Ws[k][m] = Wp[(size_t)(n0+m)*DM + k0 + k];
        }
        __syncthreads();
        #pragma unroll
        for (int k = 0; k < BK; k++) {
            float a[4], b[4];
            #pragma unroll
            for (int i = 0; i < 4; i++) a[i] = Xs[k][ty*4+i];
            #pragma unroll
            for (int j = 0; j < 4; j++) b[j] = Ws[k][tx*4+j];
            #pragma unroll
            for (int i = 0; i < 4; i++)
                #pragma unroll
                for (int j = 0; j < 4; j++) acc[i][j] += a[i]*b[j];
        }
        __syncthreads();
    }
    #pragma unroll
    for (int i = 0; i < 4; i++)
        #pragma unroll
        for (int j = 0; j < 4; j++) {
            int n = n0 + tx*4 + j;
            g_proj[(size_t)(m0+ty*4+i)*PD + n] = acc[i][j] + bp[n];
        }
}

// ---------------- gating ----------------
__global__ void gate_kernel(const float* __restrict__ sim) {
    int t = blockIdx.x * 8 + (threadIdx.x >> 5);
    int lane = threadIdx.x & 31;
    float pv[PD/32];
    float ss = 0.f;
    #pragma unroll
    for (int i = 0; i < PD/32; i++) {
        pv[i] = g_proj[(size_t)t*PD + lane + 32*i];
        ss += pv[i]*pv[i];
    }
    #pragma unroll
    for (int off = 16; off; off >>= 1) ss += __shfl_xor_sync(0xffffffff, ss, off);
    float inv_pn = 1.f / fmaxf(sqrtf(ss), 1e-12f);
    float scale = g_scale;
    float logit[NE];
    #pragma unroll
    for (int e = 0; e < NE; e++) {
        float d = 0.f;
        #pragma unroll
        for (int i = 0; i < PD/32; i++)
            d += pv[i] * sim[(lane + 32*i)*NE + e];
        #pragma unroll
        for (int off = 16; off; off >>= 1) d += __shfl_xor_sync(0xffffffff, d, off);
        logit[e] = d * inv_pn * g_inv_simnorm[e] * scale;
    }
    float mx = logit[0];
    #pragma unroll
    for (int e = 1; e < NE; e++) mx = fmaxf(mx, logit[e]);
    float pr[NE], se = 0.f;
    #pragma unroll
    for (int e = 0; e < NE; e++) { pr[e] = expf(logit[e]-mx); se += pr[e]; }
    float inv_se = 1.f / se;
    #pragma unroll
    for (int e = 0; e < NE; e++) pr[e] *= inv_se;
    int i0 = 0;
    #pragma unroll
    for (int e = 1; e < NE; e++) if (pr[e] > pr[i0]) i0 = e;
    int i1 = (i0 == 0) ? 1 : 0;
    #pragma unroll
    for (int e = 0; e < NE; e++) if (e != i0 && pr[e] > pr[i1]) i1 = e;
    float s = pr[i0] + pr[i1] + 1e-8f;
    float w0 = pr[i0]/s, w1 = pr[i1]/s;
    if (lane == 0) {
        g_topk_e[t*2]   = i0; g_topk_e[t*2+1] = i1;
        g_topk_w[t*2]   = w0; g_topk_w[t*2+1] = w1;
        g_sumw[t] = w0 + w1;
        atomicAdd(&g_count[i0], 1);
        atomicAdd(&g_count[i1], 1);
    }
    if (lane < NE) atomicAdd(&g_frac_acc[lane], pr[lane]);
}

__global__ void scan_kernel() {
    int off = 0, toff = 0;
    for (int e = 0; e < NE; e++) {
        g_offset[e]  = off;
        g_tileoff[e] = toff;
        g_cursor[e]  = off;
        off  += g_count[e];
        toff += (g_count[e] + BMM - 1) >> 7;
    }
    g_offset[NE]  = off;
    g_tileoff[NE] = toff;
}

__global__ void build_kernel() {
    int i = blockIdx.x * blockDim.x + threadIdx.x;
    if (i >= TK) return;
    int e = g_topk_e[i];
    int row = atomicAdd(&g_cursor[e], 1);
    g_token_of_row[row] = i >> 1;
    g_w_of_row[row]     = g_topk_w[i];
}

__global__ void init_out_kernel(const float* __restrict__ x, float* __restrict__ out) {
    size_t i = (size_t)blockIdx.x * blockDim.x + threadIdx.x;
    out[i] = g_sumw[i >> 10] * x[i];
}

// ---------------- TF32 WMMA grouped GEMMs: 128x128x32, cp.async double-buffer ----------------
// 8 warps, each computes a 64x32 warp tile (4x2 accumulator frags).
// Operands are PRE-ROUNDED to tf32 in global memory -> no in-loop converts.

__global__ __launch_bounds__(256) void gemm1_kernel(const float* __restrict__ a_bias) {
    extern __shared__ float dyn[];
    __shared__ int s_tok[BMM];

    int bt = blockIdx.x;
    if (bt >= g_tileoff[NE]) return;
    int e = 0;
    while (bt >= g_tileoff[e+1]) e++;
    int mloc = bt - g_tileoff[e];
    int rowbase = g_offset[e] + mloc*BMM;
    int nrows = g_count[e] - mloc*BMM; if (nrows > BMM) nrows = BMM;
    int n0 = blockIdx.y * BNN;
    int tid = threadIdx.x;
    int wid = tid >> 5;
    int wm = wid >> 2, wn = wid & 3;

    if (tid < BMM) s_tok[tid] = (tid < nrows) ? g_token_of_row[rowbase + tid] : -1;
    __syncthreads();

    float* Xb0 = dyn;
    float* Xb1 = dyn + 128*XLD;
    float* Bb0 = dyn + 2*128*XLD;
    float* Bb1 = dyn + 3*128*XLD;
    const float* x   = g_x32;
    const float* Aex = g_A32 + (size_t)e*HD*DM;

    auto load_tile = [&](int it, int buf) {
        int k0 = it * BKK;
        float* Xd = buf ? Xb1 : Xb0;
        float* Bd = buf ? Bb1 : Bb0;
        #pragma unroll
        for (int i = 0; i < 4; i++) {
            int c = tid + 256*i;
            int row = c >> 3, seg = c & 7;
            int tkn = s_tok[row];
            const float* src = (tkn >= 0) ? x + (size_t)tkn*DM + k0 + seg*4 : x;
            cp_async16(Xd + row*XLD + seg*4, src, (tkn >= 0) ? 16 : 0);
        }
        #pragma unroll
        for (int i = 0; i < 4; i++) {
            int c = tid + 256*i;
            int row = c >> 3, seg = c & 7;
            cp_async16(Bd + row*XLD + seg*4, Aex + (size_t)(n0 + row)*DM + k0 + seg*4, 16);
        }
    };

    wmma::fragment<wmma::accumulator,16,16,8,float> cfr[4][2];
    #pragma unroll
    for (int i = 0; i < 4; i++)
        #pragma unroll
        for (int j = 0; j < 2; j++) wmma::fill_fragment(cfr[i][j], 0.f);

    const int nk = DM / BKK;   // 32
    load_tile(0, 0); cp_commit();
    load_tile(1, 1); cp_commit();

    for (int it = 0; it < nk; it++) {
        if (it < nk-1) cp_wait1(); else cp_wait0();
        __syncthreads();
        float* Xs = (it & 1) ? Xb1 : Xb0;
        float* Bs = (it & 1) ? Bb1 : Bb0;
        #pragma unroll
        for (int kk = 0; kk < BKK; kk += 8) {
            wmma::fragment<wmma::matrix_a,16,16,8,wmma::precision::tf32,wmma::row_major> a[4];
            wmma::fragment<wmma::matrix_b,16,16,8,wmma::precision::tf32,wmma::col_major> b[2];
            #pragma unroll
            for (int i = 0; i < 4; i++)
                wmma::load_matrix_sync(a[i], &Xs[(wm*64 + i*16)*XLD + kk], XLD);
            #pragma unroll
            for (int j = 0; j < 2; j++)
                wmma::load_matrix_sync(b[j], &Bs[(wn*32 + j*16)*XLD + kk], XLD);
            #pragma unroll
            for (int i = 0; i < 4; i++)
                #pragma unroll
                for (int j = 0; j < 2; j++)
                    wmma::mma_sync(cfr[i][j], a[i], b[j], cfr[i][j]);
        }
        __syncthreads();
        if (it + 2 < nk) { load_tile(it+2, it & 1); cp_commit(); }
    }

    // epilogue: stage through smem, add bias, ROUND TO TF32, store H
    float* Cs = dyn;
    #pragma unroll
    for (int i = 0; i < 4; i++)
        #pragma unroll
        for (int j = 0; j < 2; j++)
            wmma::store_matrix_sync(&Cs[(wm*64 + i*16)*CLD + wn*32 + j*16], cfr[i][j], CLD, wmma::mem_row_major);
    __syncthreads();
    for (int idx = tid; idx < BMM*BNN; idx += 256) {
        int r = idx >> 7, n = idx & 127;
        if (r < nrows)
            g_H[(size_t)(rowbase+r)*HD + n0 + n] =
                wmma::__float_to_tf32(Cs[r*CLD + n] + a_bias[(size_t)e*HD + n0 + n]);
    }
}

__global__ __launch_bounds__(256) void gemm2_kernel(const float* __restrict__ b_bias,
                                                    float* __restrict__ out) {
    extern __shared__ float dyn[];
    __shared__ int   s_tok[BMM];
    __shared__ float s_w[BMM];

    int bt = blockIdx.x;
    if (bt >= g_tileoff[NE]) return;
    int e = 0;
    while (bt >= g_tileoff[e+1]) e++;
    int mloc = bt - g_tileoff[e];
    int rowbase = g_offset[e] + mloc*BMM;
    int nrows = g_count[e] - mloc*BMM; if (nrows > BMM) nrows = BMM;
    int n0 = blockIdx.y * BNN;
    int tid = threadIdx.x;
    int wid = tid >> 5;
    int wm = wid >> 2, wn = wid & 3;

    if (tid < BMM) {
        s_tok[tid] = (tid < nrows) ? g_token_of_row[rowbase + tid] : -1;
        s_w[tid]   = (tid < nrows) ? g_w_of_row[rowbase + tid] : 0.f;
    }
    __syncthreads();

    float* Xb0 = dyn;
    float* Xb1 = dyn + 128*XLD;
    float* Bb0 = dyn + 2*128*XLD;
    float* Bb1 = dyn + 3*128*XLD;
    const float* Bex = g_B32 + (size_t)e*DM*HD;

    auto load_tile = [&](int it, int buf) {
        int k0 = it * BKK;
        float* Xd = buf ? Xb1 : Xb0;
        float* Bd = buf ? Bb1 : Bb0;
        #pragma unroll
        for (int i = 0; i < 4; i++) {
            int c = tid + 256*i;
            int row = c >> 3, seg = c & 7;
            bool v = (row < nrows);
            const float* src = v ? g_H + (size_t)(rowbase+row)*HD + k0 + seg*4 : g_H;
            cp_async16(Xd + row*XLD + seg*4, src, v ? 16 : 0);
        }
        #pragma unroll
        for (int i = 0; i < 4; i++) {
            int c = tid + 256*i;
            int row = c >> 3, seg = c & 7;
            cp_async16(Bd + row*XLD + seg*4, Bex + (size_t)(n0 + row)*HD + k0 + seg*4, 16);
        }
    };

    wmma::fragment<wmma::accumulator,16,16,8,float> cfr[4][2];
    #pragma unroll
    for (int i = 0; i < 4; i++)
        #pragma unroll
        for (int j = 0; j < 2; j++) wmma::fill_fragment(cfr[i][j], 0.f);

    const int nk = HD / BKK;   // 128
    load_tile(0, 0); cp_commit();
    load_tile(1, 1); cp_commit();

    for (int it = 0; it < nk; it++) {
        if (it < nk-1) cp_wait1(); else cp_wait0();
        __syncthreads();
        float* Xs = (it & 1) ? Xb1 : Xb0;
        float* Bs = (it & 1) ? Bb1 : Bb0;
        #pragma unroll
        for (int kk = 0; kk < BKK; kk += 8) {
            wmma::fragment<wmma::matrix_a,16,16,8,wmma::precision::tf32,wmma::row_major> a[4];
            wmma::fragment<wmma::matrix_b,16,16,8,wmma::precision::tf32,wmma::col_major> b[2];
            #pragma unroll
            for (int i = 0; i < 4; i++)
                wmma::load_matrix_sync(a[i], &Xs[(wm*64 + i*16)*XLD + kk], XLD);
            #pragma unroll
            for (int j = 0; j < 2; j++)
                wmma::load_matrix_sync(b[j], &Bs[(wn*32 + j*16)*XLD + kk], XLD);
            #pragma unroll
            for (int i = 0; i < 4; i++)
                #pragma unroll
                for (int j = 0; j < 2; j++)
                    wmma::mma_sync(cfr[i][j], a[i], b[j], cfr[i][j]);
        }
        __syncthreads();
        if (it + 2 < nk) { load_tile(it+2, it & 1); cp_commit(); }
    }

    float* Cs = dyn;
    #pragma unroll
    for (int i = 0; i < 4; i++)
        #pragma unroll
        for (int j = 0; j < 2; j++)
            wmma::store_matrix_sync(&Cs[(wm*64 + i*16)*CLD + wn*32 + j*16], cfr[i][j], CLD, wmma::mem_row_major);
    __syncthreads();
    for (int idx = tid; idx < BMM*BNN; idx += 256) {
        int r = idx >> 7, n = idx & 127;
        if (r < nrows) {
            float v = Cs[r*CLD + n] + b_bias[(size_t)e*DM + n0 + n];
            atomicAdd(&out[(size_t)s_tok[r]*DM + n0 + n], s_w[r] * v);
        }
    }
}

__global__ void finalize_kernel(float* __restrict__ out) {
    if (threadIdx.x != 0) return;
    const size_t base = (size_t)TOK * DM;
    float aux = 0.f;
    for (int e = 0; e < NE; e++) {
        float fr = g_frac_acc[e] / (float)TOK;
        float d = fr - 1.f/(float)NE;
        aux += d*d;
        out[base + 1 + e]  = fr;
        out[base + 9 + e]  = (float)g_count[e];
    }
    out[base] = aux;
}

// ---------------- launch ----------------
extern "C" void kernel_launch(void* const* d_in, const int* in_sizes, int n_in,
                              void* d_out, int out_size) {
    const float* x      = (const float*)d_in[0];
    const float* Wp     = (const float*)d_in[1];
    const float* bp     = (const float*)d_in[2];
    const float* sim    = (const float*)d_in[3];
    const float* temp   = (const float*)d_in[4];
    const float* A      = (const float*)d_in[5];
    const float* a_bias = (const float*)d_in[6];
    const float* Bw     = (const float*)d_in[7];
    const float* b_bias = (const float*)d_in[8];
    float* out = (float*)d_out;

    // idempotent device-state config; safe under graph capture
    cudaFuncSetAttribute(gemm1_kernel, cudaFuncAttributeMaxDynamicSharedMemorySize, GEMM_SMEM);
    cudaFuncSetAttribute(gemm2_kernel, cudaFuncAttributeMaxDynamicSharedMemorySize, GEMM_SMEM);

    reset_kernel<<<1, 32>>>();
    prep_kernel<<<1, 256>>>(sim, temp);
    proj_kernel<<<dim3(TOK/64, PD/64), 256>>>(x, Wp, bp);
    gate_kernel<<<TOK/8, 256>>>(sim);
    scan_kernel<<<1, 1>>>();
    build_kernel<<<TK/256, 256>>>();
    init_out_kernel<<<(TOK*DM)/256, 256>>>(x, out);

    // pre-round operands to tf32 (RN); destination chosen device-side by selector
    tf32_round_kernel<<<(TOK*DM/4 + 255)/256, 256>>>(x,  0, TOK*DM/4);
    tf32_round_kernel<<<(NE*HD*DM/4 + 255)/256, 256>>>(A,  1, NE*HD*DM/4);
    tf32_round_kernel<<<(NE*DM*HD/4 + 255)/256, 256>>>(Bw, 2, NE*DM*HD/4);

    gemm1_kernel<<<dim3(NTILES, HD/BNN), 256, GEMM_SMEM>>>(a_bias);
    gemm2_kernel<<<dim3(NTILES, DM/BNN), 256, GEMM_SMEM>>>(b_bias, out);
    finalize_kernel<<<1, 32>>>(out);
}

// round 13
// speedup vs baseline: 2.0315x; 2.0315x over previous
#include <cuda_runtime.h>
#include <cuda_bf16.h>
#include <mma.h>
#include <math.h>
#include <cstdint>
#include <cstddef>

using namespace nvcuda;

// Problem constants
#define TOK   4096          // B*S tokens
#define DM    1024          // d_model
#define NE    8             // experts
#define KSEL  2             // top-k
#define HD    4096          // expert dim
#define PD    256           // proj dim
#define TK    (TOK*KSEL)    // 8192 token-expert rows
#define CLAMP_MAX 4.6051701859880914f

// GEMM tiling: 128x128 block, K-tile 32, bf16 hi/lo operands
#define BMM 128
#define BNN 128
#define BKK 32
#define XLDH 40             // smem leading dim in halves (80B rows)
#define CLD 132             // epilogue staging leading dim (floats)
#define NTILES 72           // max m-tiles: TK/128 + NE
// stage layout (halves): XH | XL | BH | BL, each 128*40 = 5120 halves (10240 B)
#define OPH 5120
#define STAGE_H (4*OPH)     // 20480 halves = 40960 B
#define GEMM_SMEM (2*STAGE_H*2)   // 81920 B; epilogue Cs 128*132*4=67584 reuses it

// ---------------- device scratch (static; no allocation) ----------------
__device__ float g_proj[TOK*PD];
__device__ int   g_topk_e[TK];
__device__ float g_topk_w[TK];
__device__ float g_sumw[TOK];
__device__ int   g_count[NE];
__device__ int   g_offset[NE+1];
__device__ int   g_tileoff[NE+1];
__device__ int   g_cursor[NE];
__device__ int   g_token_of_row[TK];
__device__ float g_w_of_row[TK];
__device__ float g_frac_acc[NE];
__device__ float g_inv_simnorm[NE];
__device__ float g_scale;

// hi/lo bf16 decompositions
__device__ __align__(256) __nv_bfloat16 g_xh[(size_t)TOK*DM];
__device__ __align__(256) __nv_bfloat16 g_xl[(size_t)TOK*DM];
__device__ __align__(256) __nv_bfloat16 g_Ah[(size_t)NE*HD*DM];
__device__ __align__(256) __nv_bfloat16 g_Al[(size_t)NE*HD*DM];
__device__ __align__(256) __nv_bfloat16 g_Bh[(size_t)NE*DM*HD];
__device__ __align__(256) __nv_bfloat16 g_Bl[(size_t)NE*DM*HD];
__device__ __align__(256) __nv_bfloat16 g_Hh[(size_t)TK*HD];
__device__ __align__(256) __nv_bfloat16 g_Hl[(size_t)TK*HD];

// ---------------- cp.async helpers ----------------
__device__ __forceinline__ void cp_async16(void* smem_dst, const void* gsrc, int src_bytes) {
    unsigned s = (unsigned)__cvta_generic_to_shared(smem_dst);
    asm volatile("cp.async.cg.shared.global [%0], [%1], 16, %2;\n"
                 :: "r"(s), "l"(gsrc), "r"(src_bytes));
}
__device__ __forceinline__ void cp_commit() { asm volatile("cp.async.commit_group;\n" ::: "memory"); }
__device__ __forceinline__ void cp_wait1()  { asm volatile("cp.async.wait_group 1;\n" ::: "memory"); }
__device__ __forceinline__ void cp_wait0()  { asm volatile("cp.async.wait_group 0;\n" ::: "memory"); }

// ---------------- small utility kernels ----------------
__global__ void reset_kernel() {
    int i = threadIdx.x;
    if (i < NE) { g_count[i] = 0; g_frac_acc[i] = 0.f; }
}

__global__ void prep_kernel(const float* __restrict__ sim, const float* __restrict__ temp) {
    int w = threadIdx.x >> 5, lane = threadIdx.x & 31;
    float ss = 0.f;
    for (int i = 0; i < PD/32; i++) {
        float v = sim[(lane + 32*i)*NE + w];
        ss += v*v;
    }
    #pragma unroll
    for (int off = 16; off; off >>= 1) ss += __shfl_xor_sync(0xffffffff, ss, off);
    if (lane == 0) g_inv_simnorm[w] = 1.f / fmaxf(sqrtf(ss), 1e-12f);
    if (threadIdx.x == 0) g_scale = expf(fminf(temp[0], CLAMP_MAX));
}

// hi/lo bf16 split, float4-vectorized.
// Destination pair is selected IN DEVICE CODE (device symbols must never be
// passed as host-side kernel arguments: on GB300 the host shadow address is
// ATS-accessible and writes silently land in host memory — the R8/R9 bug).
__global__ void hilo_kernel(const float* __restrict__ src, int which, int n4) {
    __nv_bfloat16* hi = (which == 0) ? g_xh : (which == 1) ? g_Ah : g_Bh;
    __nv_bfloat16* lo = (which == 0) ? g_xl : (which == 1) ? g_Al : g_Bl;
    int i = blockIdx.x * blockDim.x + threadIdx.x;
    if (i >= n4) return;
    float4 v = reinterpret_cast<const float4*>(src)[i];
    __nv_bfloat16 h0 = __float2bfloat16(v.x), h1 = __float2bfloat16(v.y);
    __nv_bfloat16 h2 = __float2bfloat16(v.z), h3 = __float2bfloat16(v.w);
    __nv_bfloat16 l0 = __float2bfloat16(v.x - __bfloat162float(h0));
    __nv_bfloat16 l1 = __float2bfloat16(v.y - __bfloat162float(h1));
    __nv_bfloat16 l2 = __float2bfloat16(v.z - __bfloat162float(h2));
    __nv_bfloat16 l3 = __float2bfloat16(v.w - __bfloat162float(h3));
    __nv_bfloat162 p;
    p.x = h0; p.y = h1; reinterpret_cast<__nv_bfloat162*>(hi)[2*i]   = p;
    p.x = h2; p.y = h3; reinterpret_cast<__nv_bfloat162*>(hi)[2*i+1] = p;
    p.x = l0; p.y = l1; reinterpret_cast<__nv_bfloat162*>(lo)[2*i]   = p;
    p.x = l2; p.y = l3; reinterpret_cast<__nv_bfloat162*>(lo)[2*i+1] = p;
}

// ---------------- projection: proj = x @ Wp^T + bp (fp32 SIMT, exact) ----------------
__global__ void proj_kernel(const float* __restrict__ x, const float* __restrict__ Wp,
                            const float* __restrict__ bp) {
    const int BM = 64, BN = 64, BK = 16;
    __shared__ float Xs[BK][BM+2];
    __shared__ float Ws[BK][BN+2];
    int m0 = blockIdx.x * BM, n0 = blockIdx.y * BN;
    int tid = threadIdx.x;
    int ty = tid >> 4, tx = tid & 15;
    float acc[4][4];
    #pragma unroll
    for (int i = 0; i < 4; i++)
        #pragma unroll
        for (int j = 0; j < 4; j++) acc[i][j] = 0.f;

    for (int k0 = 0; k0 < DM; k0 += BK) {
        for (int idx = tid; idx < BM*BK; idx += 256) {
            int m = idx >> 4, k = idx & 15;
            Xs[k][m] = x[(size_t)(m0+m)*DM + k0 + k];
            Ws[k][m] = Wp[(size_t)(n0+m)*DM + k0 + k];
        }
        __syncthreads();
        #pragma unroll
        for (int k = 0; k < BK; k++) {
            float a[4], b[4];
            #pragma unroll
            for (int i = 0; i < 4; i++) a[i] = Xs[k][ty*4+i];
            #pragma unroll
            for (int j = 0; j < 4; j++) b[j] = Ws[k][tx*4+j];
            #pragma unroll
            for (int i = 0; i < 4; i++)
                #pragma unroll
                for (int j = 0; j < 4; j++) acc[i][j] += a[i]*b[j];
        }
        __syncthreads();
    }
    #pragma unroll
    for (int i = 0; i < 4; i++)
        #pragma unroll
        for (int j = 0; j < 4; j++) {
            int n = n0 + tx*4 + j;
            g_proj[(size_t)(m0+ty*4+i)*PD + n] = acc[i][j] + bp[n];
        }
}

// ---------------- gating ----------------
__global__ void gate_kernel(const float* __restrict__ sim) {
    int t = blockIdx.x * 8 + (threadIdx.x >> 5);
    int lane = threadIdx.x & 31;
    float pv[PD/32];
    float ss = 0.f;
    #pragma unroll
    for (int i = 0; i < PD/32; i++) {
        pv[i] = g_proj[(size_t)t*PD + lane + 32*i];
        ss += pv[i]*pv[i];
    }
    #pragma unroll
    for (int off = 16; off; off >>= 1) ss += __shfl_xor_sync(0xffffffff, ss, off);
    float inv_pn = 1.f / fmaxf(sqrtf(ss), 1e-12f);
    float scale = g_scale;
    float logit[NE];
    #pragma unroll
    for (int e = 0; e < NE; e++) {
        float d = 0.f;
        #pragma unroll
        for (int i = 0; i < PD/32; i++)
            d += pv[i] * sim[(lane + 32*i)*NE + e];
        #pragma unroll
        for (int off = 16; off; off >>= 1) d += __shfl_xor_sync(0xffffffff, d, off);
        logit[e] = d * inv_pn * g_inv_simnorm[e] * scale;
    }
    float mx = logit[0];
    #pragma unroll
    for (int e = 1; e < NE; e++) mx = fmaxf(mx, logit[e]);
    float pr[NE], se = 0.f;
    #pragma unroll
    for (int e = 0; e < NE; e++) { pr[e] = expf(logit[e]-mx); se += pr[e]; }
    float inv_se = 1.f / se;
    #pragma unroll
    for (int e = 0; e < NE; e++) pr[e] *= inv_se;
    int i0 = 0;
    #pragma unroll
    for (int e = 1; e < NE; e++) if (pr[e] > pr[i0]) i0 = e;
    int i1 = (i0 == 0) ? 1 : 0;
    #pragma unroll
    for (int e = 0; e < NE; e++) if (e != i0 && pr[e] > pr[i1]) i1 = e;
    float s = pr[i0] + pr[i1] + 1e-8f;
    float w0 = pr[i0]/s, w1 = pr[i1]/s;
    if (lane == 0) {
        g_topk_e[t*2]   = i0; g_topk_e[t*2+1] = i1;
        g_topk_w[t*2]   = w0; g_topk_w[t*2+1] = w1;
        g_sumw[t] = w0 + w1;
        atomicAdd(&g_count[i0], 1);
        atomicAdd(&g_count[i1], 1);
    }
    if (lane < NE) atomicAdd(&g_frac_acc[lane], pr[lane]);
}

__global__ void scan_kernel() {
    int off = 0, toff = 0;
    for (int e = 0; e < NE; e++) {
        g_offset[e]  = off;
        g_tileoff[e] = toff;
        g_cursor[e]  = off;
        off  += g_count[e];
        toff += (g_count[e] + BMM - 1) >> 7;
    }
    g_offset[NE]  = off;
    g_tileoff[NE] = toff;
}

__global__ void build_kernel() {
    int i = blockIdx.x * blockDim.x + threadIdx.x;
    if (i >= TK) return;
    int e = g_topk_e[i];
    int row = atomicAdd(&g_cursor[e], 1);
    g_token_of_row[row] = i >> 1;
    g_w_of_row[row]     = g_topk_w[i];
}

__global__ void init_out_kernel(const float* __restrict__ x, float* __restrict__ out) {
    size_t i = (size_t)blockIdx.x * blockDim.x + threadIdx.x;
    out[i] = g_sumw[i >> 10] * x[i];
}

// ---------------- bf16 hi/lo WMMA grouped GEMMs: 128x128x32, cp.async double-buffer ----
// 8 warps, each computes a 64x32 warp tile (4x2 fp32 accumulator frags).
// D = Xh*Bh + Xh*Bl + Xl*Bh (3-pass bf16, ~fp32 accuracy; al*bl term ~2^-16 dropped).

typedef wmma::fragment<wmma::matrix_a,16,16,16,__nv_bfloat16,wmma::row_major> FragA;
typedef wmma::fragment<wmma::matrix_b,16,16,16,__nv_bfloat16,wmma::col_major> FragB;
typedef wmma::fragment<wmma::accumulator,16,16,16,float> FragC;

__global__ __launch_bounds__(256) void gemm1_kernel(const float* __restrict__ a_bias) {
    extern __shared__ __nv_bfloat16 dyn[];
    __shared__ int s_tok[BMM];

    int bt = blockIdx.y;
    if (bt >= g_tileoff[NE]) return;
    int e = 0;
    while (bt >= g_tileoff[e+1]) e++;
    int mloc = bt - g_tileoff[e];
    int rowbase = g_offset[e] + mloc*BMM;
    int nrows = g_count[e] - mloc*BMM; if (nrows > BMM) nrows = BMM;
    int n0 = blockIdx.x * BNN;
    int tid = threadIdx.x;
    int wid = tid >> 5;
    int wm = wid >> 2, wn = wid & 3;

    if (tid < BMM) s_tok[tid] = (tid < nrows) ? g_token_of_row[rowbase + tid] : -1;
    __syncthreads();

    const __nv_bfloat16* Wh = g_Ah + (size_t)e*HD*DM;
    const __nv_bfloat16* Wl = g_Al + (size_t)e*HD*DM;

    auto load_stage = [&](int it, int buf) {
        int k0 = it * BKK;
        __nv_bfloat16* st = dyn + buf*STAGE_H;
        #pragma unroll
        for (int i = 0; i < 2; i++) {
            int c = tid + 256*i;
            int row = c >> 2, ch = c & 3;
            int dst = row*XLDH + ch*8;
            int tkn = s_tok[row];
            int nb = (tkn >= 0) ? 16 : 0;
            size_t xo = (size_t)((tkn >= 0) ? tkn : 0)*DM + k0 + ch*8;
            cp_async16(st + dst,         g_xh + xo, nb);
            cp_async16(st + OPH + dst,   g_xl + xo, nb);
            size_t bo = (size_t)(n0 + row)*DM + k0 + ch*8;
            cp_async16(st + 2*OPH + dst, Wh + bo, 16);
            cp_async16(st + 3*OPH + dst, Wl + bo, 16);
        }
    };

    FragC cfr[4][2];
    #pragma unroll
    for (int i = 0; i < 4; i++)
        #pragma unroll
        for (int j = 0; j < 2; j++) wmma::fill_fragment(cfr[i][j], 0.f);

    const int nk = DM / BKK;   // 32
    load_stage(0, 0); cp_commit();
    load_stage(1, 1); cp_commit();

    for (int it = 0; it < nk; it++) {
        if (it < nk-1) cp_wait1(); else cp_wait0();
        __syncthreads();
        const __nv_bfloat16* st = dyn + (it & 1)*STAGE_H;
        #pragma unroll
        for (int kk = 0; kk < BKK; kk += 16) {
            FragA ah[4], al[4];
            FragB bh[2], bl[2];
            #pragma unroll
            for (int i = 0; i < 4; i++)
                wmma::load_matrix_sync(ah[i], st + (wm*64 + i*16)*XLDH + kk, XLDH);
            #pragma unroll
            for (int j = 0; j < 2; j++)
                wmma::load_matrix_sync(bh[j], st + 2*OPH + (wn*32 + j*16)*XLDH + kk, XLDH);
            #pragma unroll
            for (int i = 0; i < 4; i++)
                #pragma unroll
                for (int j = 0; j < 2; j++)
                    wmma::mma_sync(cfr[i][j], ah[i], bh[j], cfr[i][j]);
            #pragma unroll
            for (int j = 0; j < 2; j++)
                wmma::load_matrix_sync(bl[j], st + 3*OPH + (wn*32 + j*16)*XLDH + kk, XLDH);
            #pragma unroll
            for (int i = 0; i < 4; i++)
                #pragma unroll
                for (int j = 0; j < 2; j++)
                    wmma::mma_sync(cfr[i][j], ah[i], bl[j], cfr[i][j]);
            #pragma unroll
            for (int i = 0; i < 4; i++)
                wmma::load_matrix_sync(al[i], st + OPH + (wm*64 + i*16)*XLDH + kk, XLDH);
            #pragma unroll
            for (int i = 0; i < 4; i++)
                #pragma unroll
                for (int j = 0; j < 2; j++)
                    wmma::mma_sync(cfr[i][j], al[i], bh[j], cfr[i][j]);
        }
        __syncthreads();
        if (it + 2 < nk) { load_stage(it+2, it & 1); cp_commit(); }
    }

    // epilogue: stage through smem, add bias, hi/lo split into g_Hh/g_Hl
    float* Cs = (float*)dyn;
    #pragma unroll
    for (int i = 0; i < 4; i++)
        #pragma unroll
        for (int j = 0; j < 2; j++)
            wmma::store_matrix_sync(&Cs[(wm*64 + i*16)*CLD + wn*32 + j*16], cfr[i][j], CLD, wmma::mem_row_major);
    __syncthreads();
    for (int idx = tid; idx < BMM*BNN/2; idx += 256) {
        int r = idx >> 6, n = (idx & 63) * 2;
        if (r < nrows) {
            float v0 = Cs[r*CLD + n]     + a_bias[(size_t)e*HD + n0 + n];
            float v1 = Cs[r*CLD + n + 1] + a_bias[(size_t)e*HD + n0 + n + 1];
            __nv_bfloat16 h0 = __float2bfloat16(v0);
            __nv_bfloat16 h1 = __float2bfloat16(v1);
            __nv_bfloat16 l0 = __float2bfloat16(v0 - __bfloat162float(h0));
            __nv_bfloat16 l1 = __float2bfloat16(v1 - __bfloat162float(h1));
            size_t go = (size_t)(rowbase+r)*HD + n0 + n;
            __nv_bfloat162 p;
            p.x = h0; p.y = h1; *reinterpret_cast<__nv_bfloat162*>(&g_Hh[go]) = p;
            p.x = l0; p.y = l1; *reinterpret_cast<__nv_bfloat162*>(&g_Hl[go]) = p;
        }
    }
}

__global__ __launch_bounds__(256) void gemm2_kernel(const float* __restrict__ b_bias,
                                                    float* __restrict__ out) {
    extern __shared__ __nv_bfloat16 dyn[];
    __shared__ int   s_tok[BMM];
    __shared__ float s_w[BMM];

    int bt = blockIdx.y;
    if (bt >= g_tileoff[NE]) return;
    int e = 0;
    while (bt >= g_tileoff[e+1]) e++;
    int mloc = bt - g_tileoff[e];
    int rowbase = g_offset[e] + mloc*BMM;
    int nrows = g_count[e] - mloc*BMM; if (nrows > BMM) nrows = BMM;
    int n0 = blockIdx.x * BNN;
    int tid = threadIdx.x;
    int wid = tid >> 5;
    int wm = wid >> 2, wn = wid & 3;

    if (tid < BMM) {
        s_tok[tid] = (tid < nrows) ? g_token_of_row[rowbase + tid] : -1;
        s_w[tid]   = (tid < nrows) ? g_w_of_row[rowbase + tid] : 0.f;
    }
    __syncthreads();

    const __nv_bfloat16* Wh = g_Bh + (size_t)e*DM*HD;
    const __nv_bfloat16* Wl = g_Bl + (size_t)e*DM*HD;

    auto load_stage = [&](int it, int buf) {
        int k0 = it * BKK;
        __nv_bfloat16* st = dyn + buf*STAGE_H;
        #pragma unroll
        for (int i = 0; i < 2; i++) {
            int c = tid + 256*i;
            int row = c >> 2, ch = c & 3;
            int dst = row*XLDH + ch*8;
            bool v = (row < nrows);
            int nb = v ? 16 : 0;
            size_t xo = (size_t)(rowbase + (v ? row : 0))*HD + k0 + ch*8;
            cp_async16(st + dst,         g_Hh + xo, nb);
            cp_async16(st + OPH + dst,   g_Hl + xo, nb);
            size_t bo = (size_t)(n0 + row)*HD + k0 + ch*8;
            cp_async16(st + 2*OPH + dst, Wh + bo, 16);
            cp_async16(st + 3*OPH + dst, Wl + bo, 16);
        }
    };

    FragC cfr[4][2];
    #pragma unroll
    for (int i = 0; i < 4; i++)
        #pragma unroll
        for (int j = 0; j < 2; j++) wmma::fill_fragment(cfr[i][j], 0.f);

    const int nk = HD / BKK;   // 128
    load_stage(0, 0); cp_commit();
    load_stage(1, 1); cp_commit();

    for (int it = 0; it < nk; it++) {
        if (it < nk-1) cp_wait1(); else cp_wait0();
        __syncthreads();
        const __nv_bfloat16* st = dyn + (it & 1)*STAGE_H;
        #pragma unroll
        for (int kk = 0; kk < BKK; kk += 16) {
            FragA ah[4], al[4];
            FragB bh[2], bl[2];
            #pragma unroll
            for (int i = 0; i < 4; i++)
                wmma::load_matrix_sync(ah[i], st + (wm*64 + i*16)*XLDH + kk, XLDH);
            #pragma unroll
            for (int j = 0; j < 2; j++)
                wmma::load_matrix_sync(bh[j], st + 2*OPH + (wn*32 + j*16)*XLDH + kk, XLDH);
            #pragma unroll
            for (int i = 0; i < 4; i++)
                #pragma unroll
                for (int j = 0; j < 2; j++)
                    wmma::mma_sync(cfr[i][j], ah[i], bh[j], cfr[i][j]);
            #pragma unroll
            for (int j = 0; j < 2; j++)
                wmma::load_matrix_sync(bl[j], st + 3*OPH + (wn*32 + j*16)*XLDH + kk, XLDH);
            #pragma unroll
            for (int i = 0; i < 4; i++)
                #pragma unroll
                for (int j = 0; j < 2; j++)
                    wmma::mma_sync(cfr[i][j], ah[i], bl[j], cfr[i][j]);
            #pragma unroll
            for (int i = 0; i < 4; i++)
                wmma::load_matrix_sync(al[i], st + OPH + (wm*64 + i*16)*XLDH + kk, XLDH);
            #pragma unroll
            for (int i = 0; i < 4; i++)
                #pragma unroll
                for (int j = 0; j < 2; j++)
                    wmma::mma_sync(cfr[i][j], al[i], bh[j], cfr[i][j]);
        }
        __syncthreads();
        if (it + 2 < nk) { load_stage(it+2, it & 1); cp_commit(); }
    }

    float* Cs = (float*)dyn;
    #pragma unroll
    for (int i = 0; i < 4; i++)
        #pragma unroll
        for (int j = 0; j < 2; j++)
            wmma::store_matrix_sync(&Cs[(wm*64 + i*16)*CLD + wn*32 + j*16], cfr[i][j], CLD, wmma::mem_row_major);
    __syncthreads();
    for (int idx = tid; idx < BMM*BNN; idx += 256) {
        int r = idx >> 7, n = idx & 127;
        if (r < nrows) {
            float v = Cs[r*CLD + n] + b_bias[(size_t)e*DM + n0 + n];
            atomicAdd(&out[(size_t)s_tok[r]*DM + n0 + n], s_w[r] * v);
        }
    }
}

__global__ void finalize_kernel(float* __restrict__ out) {
    if (threadIdx.x != 0) return;
    const size_t base = (size_t)TOK * DM;
    float aux = 0.f;
    for (int e = 0; e < NE; e++) {
        float fr = g_frac_acc[e] / (float)TOK;
        float d = fr - 1.f/(float)NE;
        aux += d*d;
        out[base + 1 + e]  = fr;
        out[base + 9 + e]  = (float)g_count[e];
    }
    out[base] = aux;
}

// ---------------- launch ----------------
extern "C" void kernel_launch(void* const* d_in, const int* in_sizes, int n_in,
                              void* d_out, int out_size) {
    const float* x      = (const float*)d_in[0];
    const float* Wp     = (const float*)d_in[1];
    const float* bp     = (const float*)d_in[2];
    const float* sim    = (const float*)d_in[3];
    const float* temp   = (const float*)d_in[4];
    const float* A      = (const float*)d_in[5];
    const float* a_bias = (const float*)d_in[6];
    const float* Bw     = (const float*)d_in[7];
    const float* b_bias = (const float*)d_in[8];
    float* out = (float*)d_out;

    // idempotent device-state config; safe under graph capture
    cudaFuncSetAttribute(gemm1_kernel, cudaFuncAttributeMaxDynamicSharedMemorySize, GEMM_SMEM);
    cudaFuncSetAttribute(gemm2_kernel, cudaFuncAttributeMaxDynamicSharedMemorySize, GEMM_SMEM);

    reset_kernel<<<1, 32>>>();
    prep_kernel<<<1, 256>>>(sim, temp);
    proj_kernel<<<dim3(TOK/64, PD/64), 256>>>(x, Wp, bp);
    gate_kernel<<<TOK/8, 256>>>(sim);
    scan_kernel<<<1, 1>>>();
    build_kernel<<<TK/256, 256>>>();
    init_out_kernel<<<(TOK*DM)/256, 256>>>(x, out);

    // hi/lo bf16 decompositions; destination chosen device-side by selector
    hilo_kernel<<<(TOK*DM/4 + 255)/256, 256>>>(x,  0, TOK*DM/4);
    hilo_kernel<<<(NE*HD*DM/4 + 255)/256, 256>>>(A,  1, NE*HD*DM/4);
    hilo_kernel<<<(NE*DM*HD/4 + 255)/256, 256>>>(Bw, 2, NE*DM*HD/4);

    gemm1_kernel<<<dim3(HD/BNN, NTILES), 256, GEMM_SMEM>>>(a_bias);
    gemm2_kernel<<<dim3(DM/BNN, NTILES), 256, GEMM_SMEM>>>(b_bias, out);
    finalize_kernel<<<1, 32>>>(out);
}

// round 14
// speedup vs baseline: 3.4688x; 1.7076x over previous
#include <cuda_runtime.h>
#include <cuda_fp16.h>
#include <mma.h>
#include <math.h>
#include <cstdint>
#include <cstddef>

using namespace nvcuda;

// Problem constants
#define TOK   4096          // B*S tokens
#define DM    1024          // d_model
#define NE    8             // experts
#define KSEL  2             // top-k
#define HD    4096          // expert dim
#define PD    256           // proj dim
#define TK    (TOK*KSEL)    // 8192 token-expert rows
#define CLAMP_MAX 4.6051701859880914f

// GEMM tiling: 128x128 block, K-tile 32, single-pass fp16 operands
#define BMM 128
#define BNN 128
#define BKK 32
#define XLDH 40             // smem leading dim in halves (80B rows: LDSM conflict-free mod 128)
#define CLD 132             // epilogue staging leading dim (floats)
#define NTILES 72           // max m-tiles: TK/128 + NE
// stage layout (halves): X | B, each 128*40 = 5120 halves (10240 B)
#define OPH 5120
#define STAGE_H (2*OPH)     // 10240 halves = 20480 B per stage
#define GEMM_SMEM 69632     // max(2 stages = 40960 B, epilogue Cs 128*132*4 = 67584 B)

// ---------------- device scratch (static; no allocation) ----------------
__device__ float g_proj[TOK*PD];
__device__ int   g_topk_e[TK];
__device__ float g_topk_w[TK];
__device__ float g_sumw[TOK];
__device__ int   g_count[NE];
__device__ int   g_offset[NE+1];
__device__ int   g_tileoff[NE+1];
__device__ int   g_cursor[NE];
__device__ int   g_token_of_row[TK];
__device__ float g_w_of_row[TK];
__device__ float g_frac_acc[NE];
__device__ float g_inv_simnorm[NE];
__device__ float g_scale;

// fp16 copies of GEMM operands
__device__ __align__(256) __half g_x16[(size_t)TOK*DM];      // 8 MB
__device__ __align__(256) __half g_A16[(size_t)NE*HD*DM];    // 67 MB
__device__ __align__(256) __half g_B16[(size_t)NE*DM*HD];    // 67 MB
__device__ __align__(256) __half g_H16[(size_t)TK*HD];       // 67 MB

// ---------------- cp.async helpers ----------------
__device__ __forceinline__ void cp_async16(void* smem_dst, const void* gsrc, int src_bytes) {
    unsigned s = (unsigned)__cvta_generic_to_shared(smem_dst);
    asm volatile("cp.async.cg.shared.global [%0], [%1], 16, %2;\n"
                 :: "r"(s), "l"(gsrc), "r"(src_bytes));
}
__device__ __forceinline__ void cp_commit() { asm volatile("cp.async.commit_group;\n" ::: "memory"); }
__device__ __forceinline__ void cp_wait1()  { asm volatile("cp.async.wait_group 1;\n" ::: "memory"); }
__device__ __forceinline__ void cp_wait0()  { asm volatile("cp.async.wait_group 0;\n" ::: "memory"); }

// ---------------- small utility kernels ----------------
__global__ void reset_kernel() {
    int i = threadIdx.x;
    if (i < NE) { g_count[i] = 0; g_frac_acc[i] = 0.f; }
}

__global__ void prep_kernel(const float* __restrict__ sim, const float* __restrict__ temp) {
    int w = threadIdx.x >> 5, lane = threadIdx.x & 31;
    float ss = 0.f;
    for (int i = 0; i < PD/32; i++) {
        float v = sim[(lane + 32*i)*NE + w];
        ss += v*v;
    }
    #pragma unroll
    for (int off = 16; off; off >>= 1) ss += __shfl_xor_sync(0xffffffff, ss, off);
    if (lane == 0) g_inv_simnorm[w] = 1.f / fmaxf(sqrtf(ss), 1e-12f);
    if (threadIdx.x == 0) g_scale = expf(fminf(temp[0], CLAMP_MAX));
}

// fp32 -> fp16 convert (RN), float4-vectorized.
// Destination is selected IN DEVICE CODE (device symbols must never be passed
// as host-side kernel arguments: on GB300 the host shadow address is
// ATS-accessible and writes silently land in host memory — the R8/R9 bug).
__global__ void h16_kernel(const float* __restrict__ src, int which, int n4) {
    __half* dst = (which == 0) ? g_x16 : (which == 1) ? g_A16 : g_B16;
    int i = blockIdx.x * blockDim.x + threadIdx.x;
    if (i >= n4) return;
    float4 v = reinterpret_cast<const float4*>(src)[i];
    __half2 p0, p1;
    p0.x = __float2half_rn(v.x); p0.y = __float2half_rn(v.y);
    p1.x = __float2half_rn(v.z); p1.y = __float2half_rn(v.w);
    reinterpret_cast<__half2*>(dst)[2*i]   = p0;
    reinterpret_cast<__half2*>(dst)[2*i+1] = p1;
}

// ---------------- projection: proj = x @ Wp^T + bp (fp32 SIMT, exact) ----------------
__global__ void proj_kernel(const float* __restrict__ x, const float* __restrict__ Wp,
                            const float* __restrict__ bp) {
    const int BM = 64, BN = 64, BK = 16;
    __shared__ float Xs[BK][BM+2];
    __shared__ float Ws[BK][BN+2];
    int m0 = blockIdx.x * BM, n0 = blockIdx.y * BN;
    int tid = threadIdx.x;
    int ty = tid >> 4, tx = tid & 15;
    float acc[4][4];
    #pragma unroll
    for (int i = 0; i < 4; i++)
        #pragma unroll
        for (int j = 0; j < 4; j++) acc[i][j] = 0.f;

    for (int k0 = 0; k0 < DM; k0 += BK) {
        for (int idx = tid; idx < BM*BK; idx += 256) {
            int m = idx >> 4, k = idx & 15;
            Xs[k][m] = x[(size_t)(m0+m)*DM + k0 + k];
            Ws[k][m] = Wp[(size_t)(n0+m)*DM + k0 + k];
        }
        __syncthreads();
        #pragma unroll
        for (int k = 0; k < BK; k++) {
            float a[4], b[4];
            #pragma unroll
            for (int i = 0; i < 4; i++) a[i] = Xs[k][ty*4+i];
            #pragma unroll
            for (int j = 0; j < 4; j++) b[j] = Ws[k][tx*4+j];
            #pragma unroll
            for (int i = 0; i < 4; i++)
                #pragma unroll
                for (int j = 0; j < 4; j++) acc[i][j] += a[i]*b[j];
        }
        __syncthreads();
    }
    #pragma unroll
    for (int i = 0; i < 4; i++)
        #pragma unroll
        for (int j = 0; j < 4; j++) {
            int n = n0 + tx*4 + j;
            g_proj[(size_t)(m0+ty*4+i)*PD + n] = acc[i][j] + bp[n];
        }
}

// ---------------- gating ----------------
__global__ void gate_kernel(const float* __restrict__ sim) {
    int t = blockIdx.x * 8 + (threadIdx.x >> 5);
    int lane = threadIdx.x & 31;
    float pv[PD/32];
    float ss = 0.f;
    #pragma unroll
    for (int i = 0; i < PD/32; i++) {
        pv[i] = g_proj[(size_t)t*PD + lane + 32*i];
        ss += pv[i]*pv[i];
    }
    #pragma unroll
    for (int off = 16; off; off >>= 1) ss += __shfl_xor_sync(0xffffffff, ss, off);
    float inv_pn = 1.f / fmaxf(sqrtf(ss), 1e-12f);
    float scale = g_scale;
    float logit[NE];
    #pragma unroll
    for (int e = 0; e < NE; e++) {
        float d = 0.f;
        #pragma unroll
        for (int i = 0; i < PD/32; i++)
            d += pv[i] * sim[(lane + 32*i)*NE + e];
        #pragma unroll
        for (int off = 16; off; off >>= 1) d += __shfl_xor_sync(0xffffffff, d, off);
        logit[e] = d * inv_pn * g_inv_simnorm[e] * scale;
    }
    float mx = logit[0];
    #pragma unroll
    for (int e = 1; e < NE; e++) mx = fmaxf(mx, logit[e]);
    float pr[NE], se = 0.f;
    #pragma unroll
    for (int e = 0; e < NE; e++) { pr[e] = expf(logit[e]-mx); se += pr[e]; }
    float inv_se = 1.f / se;
    #pragma unroll
    for (int e = 0; e < NE; e++) pr[e] *= inv_se;
    int i0 = 0;
    #pragma unroll
    for (int e = 1; e < NE; e++) if (pr[e] > pr[i0]) i0 = e;
    int i1 = (i0 == 0) ? 1 : 0;
    #pragma unroll
    for (int e = 0; e < NE; e++) if (e != i0 && pr[e] > pr[i1]) i1 = e;
    float s = pr[i0] + pr[i1] + 1e-8f;
    float w0 = pr[i0]/s, w1 = pr[i1]/s;
    if (lane == 0) {
        g_topk_e[t*2]   = i0; g_topk_e[t*2+1] = i1;
        g_topk_w[t*2]   = w0; g_topk_w[t*2+1] = w1;
        g_sumw[t] = w0 + w1;
        atomicAdd(&g_count[i0], 1);
        atomicAdd(&g_count[i1], 1);
    }
    if (lane < NE) atomicAdd(&g_frac_acc[lane], pr[lane]);
}

__global__ void scan_kernel() {
    int off = 0, toff = 0;
    for (int e = 0; e < NE; e++) {
        g_offset[e]  = off;
        g_tileoff[e] = toff;
        g_cursor[e]  = off;
        off  += g_count[e];
        toff += (g_count[e] + BMM - 1) >> 7;
    }
    g_offset[NE]  = off;
    g_tileoff[NE] = toff;
}

__global__ void build_kernel() {
    int i = blockIdx.x * blockDim.x + threadIdx.x;
    if (i >= TK) return;
    int e = g_topk_e[i];
    int row = atomicAdd(&g_cursor[e], 1);
    g_token_of_row[row] = i >> 1;
    g_w_of_row[row]     = g_topk_w[i];
}

__global__ void init_out_kernel(const float* __restrict__ x, float* __restrict__ out) {
    size_t i = (size_t)blockIdx.x * blockDim.x + threadIdx.x;
    out[i] = g_sumw[i >> 10] * x[i];
}

// ---------------- fp16 single-pass WMMA grouped GEMMs: 128x128x32, cp.async 2-stage ----
// 8 warps, each computes a 64x32 warp tile (4x2 fp32 accumulator frags).

typedef wmma::fragment<wmma::matrix_a,16,16,16,__half,wmma::row_major> FragA;
typedef wmma::fragment<wmma::matrix_b,16,16,16,__half,wmma::col_major> FragB;
typedef wmma::fragment<wmma::accumulator,16,16,16,float> FragC;

__global__ __launch_bounds__(256) void gemm1_kernel(const float* __restrict__ a_bias) {
    extern __shared__ __half dyn[];
    __shared__ int s_tok[BMM];

    int bt = blockIdx.y;
    if (bt >= g_tileoff[NE]) return;
    int e = 0;
    while (bt >= g_tileoff[e+1]) e++;
    int mloc = bt - g_tileoff[e];
    int rowbase = g_offset[e] + mloc*BMM;
    int nrows = g_count[e] - mloc*BMM; if (nrows > BMM) nrows = BMM;
    int n0 = blockIdx.x * BNN;
    int tid = threadIdx.x;
    int wid = tid >> 5;
    int wm = wid >> 2, wn = wid & 3;

    if (tid < BMM) s_tok[tid] = (tid < nrows) ? g_token_of_row[rowbase + tid] : -1;
    __syncthreads();

    const __half* W = g_A16 + (size_t)e*HD*DM;

    auto load_stage = [&](int it, int buf) {
        int k0 = it * BKK;
        __half* st = dyn + buf*STAGE_H;
        #pragma unroll
        for (int i = 0; i < 2; i++) {
            int c = tid + 256*i;
            int row = c >> 2, ch = c & 3;
            int dst = row*XLDH + ch*8;
            int tkn = s_tok[row];
            int nb = (tkn >= 0) ? 16 : 0;
            size_t xo = (size_t)((tkn >= 0) ? tkn : 0)*DM + k0 + ch*8;
            cp_async16(st + dst,       g_x16 + xo, nb);
            size_t bo = (size_t)(n0 + row)*DM + k0 + ch*8;
            cp_async16(st + OPH + dst, W + bo, 16);
        }
    };

    FragC cfr[4][2];
    #pragma unroll
    for (int i = 0; i < 4; i++)
        #pragma unroll
        for (int j = 0; j < 2; j++) wmma::fill_fragment(cfr[i][j], 0.f);

    const int nk = DM / BKK;   // 32
    load_stage(0, 0); cp_commit();
    load_stage(1, 1); cp_commit();

    for (int it = 0; it < nk; it++) {
        if (it < nk-1) cp_wait1(); else cp_wait0();
        __syncthreads();
        const __half* st = dyn + (it & 1)*STAGE_H;
        #pragma unroll
        for (int kk = 0; kk < BKK; kk += 16) {
            FragA a[4];
            FragB b[2];
            #pragma unroll
            for (int i = 0; i < 4; i++)
                wmma::load_matrix_sync(a[i], st + (wm*64 + i*16)*XLDH + kk, XLDH);
            #pragma unroll
            for (int j = 0; j < 2; j++)
                wmma::load_matrix_sync(b[j], st + OPH + (wn*32 + j*16)*XLDH + kk, XLDH);
            #pragma unroll
            for (int i = 0; i < 4; i++)
                #pragma unroll
                for (int j = 0; j < 2; j++)
                    wmma::mma_sync(cfr[i][j], a[i], b[j], cfr[i][j]);
        }
        __syncthreads();
        if (it + 2 < nk) { load_stage(it+2, it & 1); cp_commit(); }
    }

    // epilogue: stage through smem, add bias, store H as fp16
    float* Cs = (float*)dyn;
    #pragma unroll
    for (int i = 0; i < 4; i++)
        #pragma unroll
        for (int j = 0; j < 2; j++)
            wmma::store_matrix_sync(&Cs[(wm*64 + i*16)*CLD + wn*32 + j*16], cfr[i][j], CLD, wmma::mem_row_major);
    __syncthreads();
    for (int idx = tid; idx < BMM*BNN/2; idx += 256) {
        int r = idx >> 6, n = (idx & 63) * 2;
        if (r < nrows) {
            float v0 = Cs[r*CLD + n]     + a_bias[(size_t)e*HD + n0 + n];
            float v1 = Cs[r*CLD + n + 1] + a_bias[(size_t)e*HD + n0 + n + 1];
            __half2 p;
            p.x = __float2half_rn(v0);
            p.y = __float2half_rn(v1);
            *reinterpret_cast<__half2*>(&g_H16[(size_t)(rowbase+r)*HD + n0 + n]) = p;
        }
    }
}

__global__ __launch_bounds__(256) void gemm2_kernel(const float* __restrict__ b_bias,
                                                    float* __restrict__ out) {
    extern __shared__ __half dyn[];
    __shared__ int   s_tok[BMM];
    __shared__ float s_w[BMM];

    int bt = blockIdx.y;
    if (bt >= g_tileoff[NE]) return;
    int e = 0;
    while (bt >= g_tileoff[e+1]) e++;
    int mloc = bt - g_tileoff[e];
    int rowbase = g_offset[e] + mloc*BMM;
    int nrows = g_count[e] - mloc*BMM; if (nrows > BMM) nrows = BMM;
    int n0 = blockIdx.x * BNN;
    int tid = threadIdx.x;
    int wid = tid >> 5;
    int wm = wid >> 2, wn = wid & 3;

    if (tid < BMM) {
        s_tok[tid] = (tid < nrows) ? g_token_of_row[rowbase + tid] : -1;
        s_w[tid]   = (tid < nrows) ? g_w_of_row[rowbase + tid] : 0.f;
    }
    __syncthreads();

    const __half* W = g_B16 + (size_t)e*DM*HD;

    auto load_stage = [&](int it, int buf) {
        int k0 = it * BKK;
        __half* st = dyn + buf*STAGE_H;
        #pragma unroll
        for (int i = 0; i < 2; i++) {
            int c = tid + 256*i;
            int row = c >> 2, ch = c & 3;
            int dst = row*XLDH + ch*8;
            bool v = (row < nrows);
            int nb = v ? 16 : 0;
            size_t xo = (size_t)(rowbase + (v ? row : 0))*HD + k0 + ch*8;
            cp_async16(st + dst,       g_H16 + xo, nb);
            size_t bo = (size_t)(n0 + row)*HD + k0 + ch*8;
            cp_async16(st + OPH + dst, W + bo, 16);
        }
    };

    FragC cfr[4][2];
    #pragma unroll
    for (int i = 0; i < 4; i++)
        #pragma unroll
        for (int j = 0; j < 2; j++) wmma::fill_fragment(cfr[i][j], 0.f);

    const int nk = HD / BKK;   // 128
    load_stage(0, 0); cp_commit();
    load_stage(1, 1); cp_commit();

    for (int it = 0; it < nk; it++) {
        if (it < nk-1) cp_wait1(); else cp_wait0();
        __syncthreads();
        const __half* st = dyn + (it & 1)*STAGE_H;
        #pragma unroll
        for (int kk = 0; kk < BKK; kk += 16) {
            FragA a[4];
            FragB b[2];
            #pragma unroll
            for (int i = 0; i < 4; i++)
                wmma::load_matrix_sync(a[i], st + (wm*64 + i*16)*XLDH + kk, XLDH);
            #pragma unroll
            for (int j = 0; j < 2; j++)
                wmma::load_matrix_sync(b[j], st + OPH + (wn*32 + j*16)*XLDH + kk, XLDH);
            #pragma unroll
            for (int i = 0; i < 4; i++)
                #pragma unroll
                for (int j = 0; j < 2; j++)
                    wmma::mma_sync(cfr[i][j], a[i], b[j], cfr[i][j]);
        }
        __syncthreads();
        if (it + 2 < nk) { load_stage(it+2, it & 1); cp_commit(); }
    }

    float* Cs = (float*)dyn;
    #pragma unroll
    for (int i = 0; i < 4; i++)
        #pragma unroll
        for (int j = 0; j < 2; j++)
            wmma::store_matrix_sync(&Cs[(wm*64 + i*16)*CLD + wn*32 + j*16], cfr[i][j], CLD, wmma::mem_row_major);
    __syncthreads();
    for (int idx = tid; idx < BMM*BNN; idx += 256) {
        int r = idx >> 7, n = idx & 127;
        if (r < nrows) {
            float v = Cs[r*CLD + n] + b_bias[(size_t)e*DM + n0 + n];
            atomicAdd(&out[(size_t)s_tok[r]*DM + n0 + n], s_w[r] * v);
        }
    }
}

__global__ void finalize_kernel(float* __restrict__ out) {
    if (threadIdx.x != 0) return;
    const size_t base = (size_t)TOK * DM;
    float aux = 0.f;
    for (int e = 0; e < NE; e++) {
        float fr = g_frac_acc[e] / (float)TOK;
        float d = fr - 1.f/(float)NE;
        aux += d*d;
        out[base + 1 + e]  = fr;
        out[base + 9 + e]  = (float)g_count[e];
    }
    out[base] = aux;
}

// ---------------- launch ----------------
extern "C" void kernel_launch(void* const* d_in, const int* in_sizes, int n_in,
                              void* d_out, int out_size) {
    const float* x      = (const float*)d_in[0];
    const float* Wp     = (const float*)d_in[1];
    const float* bp     = (const float*)d_in[2];
    const float* sim    = (const float*)d_in[3];
    const float* temp   = (const float*)d_in[4];
    const float* A      = (const float*)d_in[5];
    const float* a_bias = (const float*)d_in[6];
    const float* Bw     = (const float*)d_in[7];
    const float* b_bias = (const float*)d_in[8];
    float* out = (float*)d_out;

    // idempotent device-state config; safe under graph capture
    cudaFuncSetAttribute(gemm1_kernel, cudaFuncAttributeMaxDynamicSharedMemorySize, GEMM_SMEM);
    cudaFuncSetAttribute(gemm2_kernel, cudaFuncAttributeMaxDynamicSharedMemorySize, GEMM_SMEM);

    reset_kernel<<<1, 32>>>();
    prep_kernel<<<1, 256>>>(sim, temp);
    proj_kernel<<<dim3(TOK/64, PD/64), 256>>>(x, Wp, bp);
    gate_kernel<<<TOK/8, 256>>>(sim);
    scan_kernel<<<1, 1>>>();
    build_kernel<<<TK/256, 256>>>();
    init_out_kernel<<<(TOK*DM)/256, 256>>>(x, out);

    // fp16 conversions; destination chosen device-side by selector
    h16_kernel<<<(TOK*DM/4 + 255)/256, 256>>>(x,  0, TOK*DM/4);
    h16_kernel<<<(NE*HD*DM/4 + 255)/256, 256>>>(A,  1, NE*HD*DM/4);
    h16_kernel<<<(NE*DM*HD/4 + 255)/256, 256>>>(Bw, 2, NE*DM*HD/4);

    gemm1_kernel<<<dim3(HD/BNN, NTILES), 256, GEMM_SMEM>>>(a_bias);
    gemm2_kernel<<<dim3(DM/BNN, NTILES), 256, GEMM_SMEM>>>(b_bias, out);
    finalize_kernel<<<1, 32>>>(out);
}

// round 16
// speedup vs baseline: 5.9446x; 1.7137x over previous
#include <cuda_runtime.h>
#include <cuda_fp16.h>
#include <mma.h>
#include <math.h>
#include <cstdint>
#include <cstddef>

using namespace nvcuda;

// Problem constants
#define TOK   4096          // B*S tokens
#define DM    1024          // d_model
#define NE    8             // experts
#define KSEL  2             // top-k
#define HD    4096          // expert dim
#define PD    256           // proj dim
#define TK    (TOK*KSEL)    // 8192 token-expert rows
#define CLAMP_MAX 4.6051701859880914f

// GEMM tiling: 128x128 block, K-tile 32, single-pass fp16 operands
#define BMM 128
#define BNN 128
#define BKK 32
#define XLDH 40             // smem leading dim in halves (80B rows)
#define CLD 132             // epilogue staging leading dim (floats)
#define NTILES 72           // max m-tiles: TK/128 + NE
// stage layout (halves): X | B, each 128*40 = 5120 halves (10240 B)
#define OPH 5120
#define STAGE_H (2*OPH)     // 10240 halves = 20480 B per stage; 3 stages = 61440 B
#define GEMM_SMEM 69632     // max(3 stages = 61440 B, epilogue Cs 128*132*4 = 67584 B)

// ---------------- device scratch (static; no allocation) ----------------
__device__ float g_proj[TOK*PD];
__device__ int   g_topk_e[TK];
__device__ float g_topk_w[TK];
__device__ float g_sumw[TOK];
__device__ int   g_count[NE];
__device__ int   g_offset[NE+1];
__device__ int   g_tileoff[NE+1];
__device__ int   g_cursor[NE];
__device__ int   g_token_of_row[TK];
__device__ float g_w_of_row[TK];
__device__ float g_frac_acc[NE];
__device__ float g_inv_simnorm[NE];
__device__ float g_scale;

// fp16 copies of GEMM operands (g_x16 = hi part of x; also GEMM1 operand)
__device__ __align__(256) __half g_x16[(size_t)TOK*DM];      // 8 MB
__device__ __align__(256) __half g_xlo[(size_t)TOK*DM];      // 8 MB (x lo, proj only)
__device__ __align__(256) __half g_Wph[PD*DM];               // 0.5 MB
__device__ __align__(256) __half g_Wpl[PD*DM];               // 0.5 MB
__device__ __align__(256) __half g_A16[(size_t)NE*HD*DM];    // 67 MB
__device__ __align__(256) __half g_B16[(size_t)NE*DM*HD];    // 67 MB
__device__ __align__(256) __half g_H16[(size_t)TK*HD];       // 67 MB

// ---------------- cp.async helpers ----------------
__device__ __forceinline__ void cp_async16(void* smem_dst, const void* gsrc, int src_bytes) {
    unsigned s = (unsigned)__cvta_generic_to_shared(smem_dst);
    asm volatile("cp.async.cg.shared.global [%0], [%1], 16, %2;\n"
                 :: "r"(s), "l"(gsrc), "r"(src_bytes));
}
__device__ __forceinline__ void cp_commit() { asm volatile("cp.async.commit_group;\n" ::: "memory"); }
__device__ __forceinline__ void cp_wait2()  { asm volatile("cp.async.wait_group 2;\n" ::: "memory"); }
__device__ __forceinline__ void cp_wait1()  { asm volatile("cp.async.wait_group 1;\n" ::: "memory"); }
__device__ __forceinline__ void cp_wait0()  { asm volatile("cp.async.wait_group 0;\n" ::: "memory"); }
__device__ __forceinline__ void cp_wait_rem(int rem) {
    if (rem >= 2) cp_wait2(); else if (rem == 1) cp_wait1(); else cp_wait0();
}

// ---------------- small utility kernels ----------------
__global__ void reset_kernel() {
    int i = threadIdx.x;
    if (i < NE) { g_count[i] = 0; g_frac_acc[i] = 0.f; }
}

__global__ void prep_kernel(const float* __restrict__ sim, const float* __restrict__ temp) {
    int w = threadIdx.x >> 5, lane = threadIdx.x & 31;
    float ss = 0.f;
    for (int i = 0; i < PD/32; i++) {
        float v = sim[(lane + 32*i)*NE + w];
        ss += v*v;
    }
    #pragma unroll
    for (int off = 16; off; off >>= 1) ss += __shfl_xor_sync(0xffffffff, ss, off);
    if (lane == 0) g_inv_simnorm[w] = 1.f / fmaxf(sqrtf(ss), 1e-12f);
    if (threadIdx.x == 0) g_scale = expf(fminf(temp[0], CLAMP_MAX));
}

// fp32 -> fp16 convert (RN), float4-vectorized; single-output (weights)
// Destination selected IN DEVICE CODE (device symbols must never be passed as
// host-side kernel args: GB300 ATS silently lands writes in host shadow memory).
__global__ void h16_kernel(const float* __restrict__ src, int which, int n4) {
    __half* dst = (which == 1) ? g_A16 : g_B16;
    int i = blockIdx.x * blockDim.x + threadIdx.x;
    if (i >= n4) return;
    float4 v = reinterpret_cast<const float4*>(src)[i];
    __half2 p0, p1;
    p0.x = __float2half_rn(v.x); p0.y = __float2half_rn(v.y);
    p1.x = __float2half_rn(v.z); p1.y = __float2half_rn(v.w);
    reinterpret_cast<__half2*>(dst)[2*i]   = p0;
    reinterpret_cast<__half2*>(dst)[2*i+1] = p1;
}

// fp32 -> fp16 hi/lo split (hi = rn(v), lo = rn(v - hi)); for x and Wp
__global__ void hilo16_kernel(const float* __restrict__ src, int which, int n4) {
    __half* hi = (which == 0) ? g_x16 : g_Wph;
    __half* lo = (which == 0) ? g_xlo : g_Wpl;
    int i = blockIdx.x * blockDim.x + threadIdx.x;
    if (i >= n4) return;
    float4 v = reinterpret_cast<const float4*>(src)[i];
    __half h0 = __float2half_rn(v.x), h1 = __float2half_rn(v.y);
    __half h2 = __float2half_rn(v.z), h3 = __float2half_rn(v.w);
    __half2 ph0, ph1, pl0, pl1;
    ph0.x = h0; ph0.y = h1; ph1.x = h2; ph1.y = h3;
    pl0.x = __float2half_rn(v.x - __half2float(h0));
    pl0.y = __float2half_rn(v.y - __half2float(h1));
    pl1.x = __float2half_rn(v.z - __half2float(h2));
    pl1.y = __float2half_rn(v.w - __half2float(h3));
    reinterpret_cast<__half2*>(hi)[2*i]   = ph0;
    reinterpret_cast<__half2*>(hi)[2*i+1] = ph1;
    reinterpret_cast<__half2*>(lo)[2*i]   = pl0;
    reinterpret_cast<__half2*>(lo)[2*i+1] = pl1;
}

typedef wmma::fragment<wmma::matrix_a,16,16,16,__half,wmma::row_major> FragA;
typedef wmma::fragment<wmma::matrix_b,16,16,16,__half,wmma::col_major> FragB;
typedef wmma::fragment<wmma::accumulator,16,16,16,float> FragC;

// ---------------- projection: proj = x @ Wp^T + bp (fp16 hi/lo 3-pass WMMA) -------
// Error ~2^-22 relative — equivalent to fp32 for the downstream top-k.
// Grid: (PD/BNN=2, TOK/BMM=32). Stages: XH|XL|WH|WL, 2-stage double buffer.
#define POPH 5120
#define PSTAGE_H (4*POPH)    // 40960 B per stage; 2 stages = 81920 B
#define PROJ_SMEM 81920

__global__ __launch_bounds__(256) void proj_kernel(const float* __restrict__ bp) {
    extern __shared__ __half dyn[];
    int m0 = blockIdx.y * BMM, n0 = blockIdx.x * BNN;
    int tid = threadIdx.x;
    int wid = tid >> 5;
    int wm = wid >> 2, wn = wid & 3;

    auto load_stage = [&](int it, int buf) {
        int k0 = it * BKK;
        __half* st = dyn + buf*PSTAGE_H;
        #pragma unroll
        for (int i = 0; i < 2; i++) {
            int c = tid + 256*i;
            int row = c >> 2, ch = c & 3;
            int dst = row*XLDH + ch*8;
            size_t xo = (size_t)(m0 + row)*DM + k0 + ch*8;
            cp_async16(st + dst,          g_x16 + xo, 16);
            cp_async16(st + POPH + dst,   g_xlo + xo, 16);
            size_t wo = (size_t)(n0 + row)*DM + k0 + ch*8;
            cp_async16(st + 2*POPH + dst, g_Wph + wo, 16);
            cp_async16(st + 3*POPH + dst, g_Wpl + wo, 16);
        }
    };

    FragC cfr[4][2];
    #pragma unroll
    for (int i = 0; i < 4; i++)
        #pragma unroll
        for (int j = 0; j < 2; j++) wmma::fill_fragment(cfr[i][j], 0.f);

    const int nk = DM / BKK;   // 32
    load_stage(0, 0); cp_commit();
    load_stage(1, 1); cp_commit();

    for (int it = 0; it < nk; it++) {
        if (it < nk-1) cp_wait1(); else cp_wait0();
        __syncthreads();
        const __half* st = dyn + (it & 1)*PSTAGE_H;
        #pragma unroll
        for (int kk = 0; kk < BKK; kk += 16) {
            FragA ah[4], al[4];
            FragB bh[2], bl[2];
            #pragma unroll
            for (int i = 0; i < 4; i++)
                wmma::load_matrix_sync(ah[i], st + (wm*64 + i*16)*XLDH + kk, XLDH);
            #pragma unroll
            for (int j = 0; j < 2; j++)
                wmma::load_matrix_sync(bh[j], st + 2*POPH + (wn*32 + j*16)*XLDH + kk, XLDH);
            #pragma unroll
            for (int i = 0; i < 4; i++)
                #pragma unroll
                for (int j = 0; j < 2; j++)
                    wmma::mma_sync(cfr[i][j], ah[i], bh[j], cfr[i][j]);
            #pragma unroll
            for (int j = 0; j < 2; j++)
                wmma::load_matrix_sync(bl[j], st + 3*POPH + (wn*32 + j*16)*XLDH + kk, XLDH);
            #pragma unroll
            for (int i = 0; i < 4; i++)
                #pragma unroll
                for (int j = 0; j < 2; j++)
                    wmma::mma_sync(cfr[i][j], ah[i], bl[j], cfr[i][j]);
            #pragma unroll
            for (int i = 0; i < 4; i++)
                wmma::load_matrix_sync(al[i], st + POPH + (wm*64 + i*16)*XLDH + kk, XLDH);
            #pragma unroll
            for (int i = 0; i < 4; i++)
                #pragma unroll
                for (int j = 0; j < 2; j++)
                    wmma::mma_sync(cfr[i][j], al[i], bh[j], cfr[i][j]);
        }
        __syncthreads();
        if (it + 2 < nk) { load_stage(it+2, it & 1); cp_commit(); }
    }

    float* Cs = (float*)dyn;
    #pragma unroll
    for (int i = 0; i < 4; i++)
        #pragma unroll
        for (int j = 0; j < 2; j++)
            wmma::store_matrix_sync(&Cs[(wm*64 + i*16)*CLD + wn*32 + j*16], cfr[i][j], CLD, wmma::mem_row_major);
    __syncthreads();
    for (int idx = tid; idx < BMM*BNN; idx += 256) {
        int r = idx >> 7, n = idx & 127;
        g_proj[(size_t)(m0+r)*PD + n0 + n] = Cs[r*CLD + n] + bp[n0 + n];
    }
}

// ---------------- gating ----------------
__global__ void gate_kernel(const float* __restrict__ sim) {
    int t = blockIdx.x * 8 + (threadIdx.x >> 5);
    int lane = threadIdx.x & 31;
    float pv[PD/32];
    float ss = 0.f;
    #pragma unroll
    for (int i = 0; i < PD/32; i++) {
        pv[i] = g_proj[(size_t)t*PD + lane + 32*i];
        ss += pv[i]*pv[i];
    }
    #pragma unroll
    for (int off = 16; off; off >>= 1) ss += __shfl_xor_sync(0xffffffff, ss, off);
    float inv_pn = 1.f / fmaxf(sqrtf(ss), 1e-12f);
    float scale = g_scale;
    float logit[NE];
    #pragma unroll
    for (int e = 0; e < NE; e++) {
        float d = 0.f;
        #pragma unroll
        for (int i = 0; i < PD/32; i++)
            d += pv[i] * sim[(lane + 32*i)*NE + e];
        #pragma unroll
        for (int off = 16; off; off >>= 1) d += __shfl_xor_sync(0xffffffff, d, off);
        logit[e] = d * inv_pn * g_inv_simnorm[e] * scale;
    }
    float mx = logit[0];
    #pragma unroll
    for (int e = 1; e < NE; e++) mx = fmaxf(mx, logit[e]);
    float pr[NE], se = 0.f;
    #pragma unroll
    for (int e = 0; e < NE; e++) { pr[e] = expf(logit[e]-mx); se += pr[e]; }
    float inv_se = 1.f / se;
    #pragma unroll
    for (int e = 0; e < NE; e++) pr[e] *= inv_se;
    int i0 = 0;
    #pragma unroll
    for (int e = 1; e < NE; e++) if (pr[e] > pr[i0]) i0 = e;
    int i1 = (i0 == 0) ? 1 : 0;
    #pragma unroll
    for (int e = 0; e < NE; e++) if (e != i0 && pr[e] > pr[i1]) i1 = e;
    float s = pr[i0] + pr[i1] + 1e-8f;
    float w0 = pr[i0]/s, w1 = pr[i1]/s;
    if (lane == 0) {
        g_topk_e[t*2]   = i0; g_topk_e[t*2+1] = i1;
        g_topk_w[t*2]   = w0; g_topk_w[t*2+1] = w1;
        g_sumw[t] = w0 + w1;
        atomicAdd(&g_count[i0], 1);
        atomicAdd(&g_count[i1], 1);
    }
    if (lane < NE) atomicAdd(&g_frac_acc[lane], pr[lane]);
}

__global__ void scan_kernel() {
    int off = 0, toff = 0;
    for (int e = 0; e < NE; e++) {
        g_offset[e]  = off;
        g_tileoff[e] = toff;
        g_cursor[e]  = off;
        off  += g_count[e];
        toff += (g_count[e] + BMM - 1) >> 7;
    }
    g_offset[NE]  = off;
    g_tileoff[NE] = toff;
}

__global__ void build_kernel() {
    int i = blockIdx.x * blockDim.x + threadIdx.x;
    if (i >= TK) return;
    int e = g_topk_e[i];
    int row = atomicAdd(&g_cursor[e], 1);
    g_token_of_row[row] = i >> 1;
    g_w_of_row[row]     = g_topk_w[i];
}

__global__ void init_out_kernel(const float* __restrict__ x, float* __restrict__ out) {
    size_t i = (size_t)blockIdx.x * blockDim.x + threadIdx.x;
    out[i] = g_sumw[i >> 10] * x[i];
}

// ---------------- fp16 single-pass WMMA grouped GEMMs: 128x128x32, 3-stage cp.async ----

__global__ __launch_bounds__(256) void gemm1_kernel(const float* __restrict__ a_bias) {
    extern __shared__ __half dyn[];
    __shared__ int s_tok[BMM];

    int bt = blockIdx.y;
    if (bt >= g_tileoff[NE]) return;
    int e = 0;
    while (bt >= g_tileoff[e+1]) e++;
    int mloc = bt - g_tileoff[e];
    int rowbase = g_offset[e] + mloc*BMM;
    int nrows = g_count[e] - mloc*BMM; if (nrows > BMM) nrows = BMM;
    int n0 = blockIdx.x * BNN;
    int tid = threadIdx.x;
    int wid = tid >> 5;
    int wm = wid >> 2, wn = wid & 3;

    if (tid < BMM) s_tok[tid] = (tid < nrows) ? g_token_of_row[rowbase + tid] : -1;
    __syncthreads();

    const __half* W = g_A16 + (size_t)e*HD*DM;

    auto load_stage = [&](int it, int buf) {
        int k0 = it * BKK;
        __half* st = dyn + buf*STAGE_H;
        #pragma unroll
        for (int i = 0; i < 2; i++) {
            int c = tid + 256*i;
            int row = c >> 2, ch = c & 3;
            int dst = row*XLDH + ch*8;
            int tkn = s_tok[row];
            int nb = (tkn >= 0) ? 16 : 0;
            size_t xo = (size_t)((tkn >= 0) ? tkn : 0)*DM + k0 + ch*8;
            cp_async16(st + dst,       g_x16 + xo, nb);
            size_t bo = (size_t)(n0 + row)*DM + k0 + ch*8;
            cp_async16(st + OPH + dst, W + bo, 16);
        }
    };

    FragC cfr[4][2];
    #pragma unroll
    for (int i = 0; i < 4; i++)
        #pragma unroll
        for (int j = 0; j < 2; j++) wmma::fill_fragment(cfr[i][j], 0.f);

    const int nk = DM / BKK;   // 32
    load_stage(0, 0); cp_commit();
    load_stage(1, 1); cp_commit();
    load_stage(2, 2); cp_commit();

    for (int it = 0; it < nk; it++) {
        cp_wait_rem(nk - it - 1);
        __syncthreads();
        const __half* st = dyn + (it % 3)*STAGE_H;
        #pragma unroll
        for (int kk = 0; kk < BKK; kk += 16) {
            FragA a[4];
            FragB b[2];
            #pragma unroll
            for (int i = 0; i < 4; i++)
                wmma::load_matrix_sync(a[i], st + (wm*64 + i*16)*XLDH + kk, XLDH);
            #pragma unroll
            for (int j = 0; j < 2; j++)
                wmma::load_matrix_sync(b[j], st + OPH + (wn*32 + j*16)*XLDH + kk, XLDH);
            #pragma unroll
            for (int i = 0; i < 4; i++)
                #pragma unroll
                for (int j = 0; j < 2; j++)
                    wmma::mma_sync(cfr[i][j], a[i], b[j], cfr[i][j]);
        }
        __syncthreads();
        if (it + 3 < nk) { load_stage(it+3, it % 3); cp_commit(); }
    }

    // epilogue: stage through smem, add bias, store H as fp16
    float* Cs = (float*)dyn;
    #pragma unroll
    for (int i = 0; i < 4; i++)
        #pragma unroll
        for (int j = 0; j < 2; j++)
            wmma::store_matrix_sync(&Cs[(wm*64 + i*16)*CLD + wn*32 + j*16], cfr[i][j], CLD, wmma::mem_row_major);
    __syncthreads();
    for (int idx = tid; idx < BMM*BNN/2; idx += 256) {
        int r = idx >> 6, n = (idx & 63) * 2;
        if (r < nrows) {
            float v0 = Cs[r*CLD + n]     + a_bias[(size_t)e*HD + n0 + n];
            float v1 = Cs[r*CLD + n + 1] + a_bias[(size_t)e*HD + n0 + n + 1];
            __half2 p;
            p.x = __float2half_rn(v0);
            p.y = __float2half_rn(v1);
            *reinterpret_cast<__half2*>(&g_H16[(size_t)(rowbase+r)*HD + n0 + n]) = p;
        }
    }
}

__global__ __launch_bounds__(256) void gemm2_kernel(const float* __restrict__ b_bias,
                                                    float* __restrict__ out) {
    extern __shared__ __half dyn[];
    __shared__ int   s_tok[BMM];
    __shared__ float s_w[BMM];

    int bt = blockIdx.y;
    if (bt >= g_tileoff[NE]) return;
    int e = 0;
    while (bt >= g_tileoff[e+1]) e++;
    int mloc = bt - g_tileoff[e];
    int rowbase = g_offset[e] + mloc*BMM;
    int nrows = g_count[e] - mloc*BMM; if (nrows > BMM) nrows = BMM;
    int n0 = blockIdx.x * BNN;
    int tid = threadIdx.x;
    int wid = tid >> 5;
    int wm = wid >> 2, wn = wid & 3;

    if (tid < BMM) {
        s_tok[tid] = (tid < nrows) ? g_token_of_row[rowbase + tid] : -1;
        s_w[tid]   = (tid < nrows) ? g_w_of_row[rowbase + tid] : 0.f;
    }
    __syncthreads();

    const __half* W = g_B16 + (size_t)e*DM*HD;

    auto load_stage = [&](int it, int buf) {
        int k0 = it * BKK;
        __half* st = dyn + buf*STAGE_H;
        #pragma unroll
        for (int i = 0; i < 2; i++) {
            int c = tid + 256*i;
            int row = c >> 2, ch = c & 3;
            int dst = row*XLDH + ch*8;
            bool v = (row < nrows);
            int nb = v ? 16 : 0;
            size_t xo = (size_t)(rowbase + (v ? row : 0))*HD + k0 + ch*8;
            cp_async16(st + dst,       g_H16 + xo, nb);
            size_t bo = (size_t)(n0 + row)*HD + k0 + ch*8;
            cp_async16(st + OPH + dst, W + bo, 16);
        }
    };

    FragC cfr[4][2];
    #pragma unroll
    for (int i = 0; i < 4; i++)
        #pragma unroll
        for (int j = 0; j < 2; j++) wmma::fill_fragment(cfr[i][j], 0.f);

    const int nk = HD / BKK;   // 128
    load_stage(0, 0); cp_commit();
    load_stage(1, 1); cp_commit();
    load_stage(2, 2); cp_commit();

    for (int it = 0; it < nk; it++) {
        cp_wait_rem(nk - it - 1);
        __syncthreads();
        const __half* st = dyn + (it % 3)*STAGE_H;
        #pragma unroll
        for (int kk = 0; kk < BKK; kk += 16) {
            FragA a[4];
            FragB b[2];
            #pragma unroll
            for (int i = 0; i < 4; i++)
                wmma::load_matrix_sync(a[i], st + (wm*64 + i*16)*XLDH + kk, XLDH);
            #pragma unroll
            for (int j = 0; j < 2; j++)
                wmma::load_matrix_sync(b[j], st + OPH + (wn*32 + j*16)*XLDH + kk, XLDH);
            #pragma unroll
            for (int i = 0; i < 4; i++)
                #pragma unroll
                for (int j = 0; j < 2; j++)
                    wmma::mma_sync(cfr[i][j], a[i], b[j], cfr[i][j]);
        }
        __syncthreads();
        if (it + 3 < nk) { load_stage(it+3, it % 3); cp_commit(); }
    }

    float* Cs = (float*)dyn;
    #pragma unroll
    for (int i = 0; i < 4; i++)
        #pragma unroll
        for (int j = 0; j < 2; j++)
            wmma::store_matrix_sync(&Cs[(wm*64 + i*16)*CLD + wn*32 + j*16], cfr[i][j], CLD, wmma::mem_row_major);
    __syncthreads();
    for (int idx = tid; idx < BMM*BNN; idx += 256) {
        int r = idx >> 7, n = idx & 127;
        if (r < nrows) {
            float v = Cs[r*CLD + n] + b_bias[(size_t)e*DM + n0 + n];
            atomicAdd(&out[(size_t)s_tok[r]*DM + n0 + n], s_w[r] * v);
        }
    }
}

__global__ void finalize_kernel(float* __restrict__ out) {
    if (threadIdx.x != 0) return;
    const size_t base = (size_t)TOK * DM;
    float aux = 0.f;
    for (int e = 0; e < NE; e++) {
        float fr = g_frac_acc[e] / (float)TOK;
        float d = fr - 1.f/(float)NE;
        aux += d*d;
        out[base + 1 + e]  = fr;
        out[base + 9 + e]  = (float)g_count[e];
    }
    out[base] = aux;
}

// ---------------- launch ----------------
extern "C" void kernel_launch(void* const* d_in, const int* in_sizes, int n_in,
                              void* d_out, int out_size) {
    const float* x      = (const float*)d_in[0];
    const float* Wp     = (const float*)d_in[1];
    const float* bp     = (const float*)d_in[2];
    const float* sim    = (const float*)d_in[3];
    const float* temp   = (const float*)d_in[4];
    const float* A      = (const float*)d_in[5];
    const float* a_bias = (const float*)d_in[6];
    const float* Bw     = (const float*)d_in[7];
    const float* b_bias = (const float*)d_in[8];
    float* out = (float*)d_out;

    // idempotent device-state config; safe under graph capture
    cudaFuncSetAttribute(gemm1_kernel, cudaFuncAttributeMaxDynamicSharedMemorySize, GEMM_SMEM);
    cudaFuncSetAttribute(gemm2_kernel, cudaFuncAttributeMaxDynamicSharedMemorySize, GEMM_SMEM);
    cudaFuncSetAttribute(proj_kernel,  cudaFuncAttributeMaxDynamicSharedMemorySize, PROJ_SMEM);

    reset_kernel<<<1, 32>>>();
    prep_kernel<<<1, 256>>>(sim, temp);

    // hi/lo split of x and Wp (proj operands; g_x16 doubles as GEMM1 operand)
    hilo16_kernel<<<(TOK*DM/4 + 255)/256, 256>>>(x,  0, TOK*DM/4);
    hilo16_kernel<<<(PD*DM/4 + 255)/256, 256>>>(Wp, 1, PD*DM/4);
    // fp16 weight conversions
    h16_kernel<<<(NE*HD*DM/4 + 255)/256, 256>>>(A,  1, NE*HD*DM/4);
    h16_kernel<<<(NE*DM*HD/4 + 255)/256, 256>>>(Bw, 2, NE*DM*HD/4);

    proj_kernel<<<dim3(PD/BNN, TOK/BMM), 256, PROJ_SMEM>>>(bp);
    gate_kernel<<<TOK/8, 256>>>(sim);
    scan_kernel<<<1, 1>>>();
    build_kernel<<<TK/256, 256>>>();
    init_out_kernel<<<(TOK*DM)/256, 256>>>(x, out);

    gemm1_kernel<<<dim3(HD/BNN, NTILES), 256, GEMM_SMEM>>>(a_bias);
    gemm2_kernel<<<dim3(DM/BNN, NTILES), 256, GEMM_SMEM>>>(b_bias, out);
    finalize_kernel<<<1, 32>>>(out);
}